// round 12
// baseline (speedup 1.0000x reference)
#include <cuda_runtime.h>
#include <cuda_bf16.h>
#include <cstdint>
#include <cstddef>

// ---------------------------------------------------------------------------
// STDP delta_w:
//   delta_w = sum_t O_t^T P_t  -  s[:,None] * W
// GEMM: K = T*B = 1024, M = POST = 4096, N = PRE = 4096, HMMA mma.sync bf16.
// R12: R11 mbarrier producer/consumer pipeline with the deadlock FIXED:
// cp.async.mbarrier.arrive must be the .noinc form when the arrival count is
// pre-accounted in mbarrier.init (default form self-increments the pending
// count -> 512 expected vs 256 delivered -> permanent hang; R11 timeout).
// Goal unchanged: remove the per-chunk __syncthreads phase-lock so the ldsm
// and mma bursts of 16 warps de-correlate (R10: pipes overlap only ~600 of
// 3543 cyc/chunk).
// ---------------------------------------------------------------------------

namespace {
constexpr int T_STEPS = 64;
constexpr int BATCH   = 16;
constexpr int PRE_N   = 4096;
constexpr int POST_N  = 4096;
constexpr int KDIM    = T_STEPS * BATCH;  // 1024

constexpr int TM = 128;
constexpr int TN = 128;
constexpr int KC = 64;                       // K elems per chunk (128 B rows)
constexpr int NCHUNK  = KDIM / KC;           // 16
constexpr int NSTAGES = 3;
constexpr int A_STAGE_BYTES = TM * 128;      // 16384
constexpr int B_STAGE_BYTES = TN * 128;      // 16384
constexpr int STAGE_BYTES   = A_STAGE_BYTES + B_STAGE_BYTES;   // 32768
constexpr int MBAR_OFF      = NSTAGES * STAGE_BYTES;           // 98304
constexpr int SMEM_TOTAL    = MBAR_OFF + 64;                   // 98368

constexpr int NB_PRE  = (BATCH * PRE_N)  / 256;  // 256
constexpr int NB_POST = (BATCH * POST_N) / 256;  // 256
}

// Scratch (device globals: allocation-free rule)
__device__ __nv_bfloat16 g_A[POST_N * KDIM];   // out_spikes^T bf16 [post][k]
__device__ __nv_bfloat16 g_B[PRE_N * KDIM];    // trace_pre^T bf16 [pre][k]
__device__ float g_spart[BATCH * POST_N];

// ---------------------------------------------------------------------------
// Combined preprocess (one launch):
//  blocks [0, NB_PRE)             : trace_pre scan -> g_B (K-major bf16)
//  blocks [NB_PRE, NB_PRE+NB_POST): out_spikes^T   -> g_A + s partials
// ---------------------------------------------------------------------------
__global__ void __launch_bounds__(256) prep_kernel(
    const float* __restrict__ in_spikes, const float* __restrict__ out_spikes)
{
    if (blockIdx.x < NB_PRE) {
        int g = blockIdx.x * 256 + threadIdx.x;
        int p = g & (PRE_N - 1);
        int b = g >> 12;
        const float* src = in_spikes + (size_t)b * PRE_N + p;
        float tp = 0.0f;
        unsigned int packed[T_STEPS / 2];
#pragma unroll
        for (int t2 = 0; t2 < T_STEPS / 2; ++t2) {
            float i0 = src[(size_t)(2 * t2)     * (BATCH * PRE_N)];
            float i1 = src[(size_t)(2 * t2 + 1) * (BATCH * PRE_N)];
            tp = fminf(fmaxf(fmaf(0.5f, tp, i0), 0.0f), 1.0f);
            float v0 = tp;
            tp = fminf(fmaxf(fmaf(0.5f, tp, i1), 0.0f), 1.0f);
            float v1 = tp;
            __nv_bfloat162 h2 = __floats2bfloat162_rn(v0, v1);
            packed[t2] = *reinterpret_cast<unsigned int*>(&h2);
        }
        uint4* dst = reinterpret_cast<uint4*>(g_B + (size_t)p * KDIM + b * T_STEPS);
#pragma unroll
        for (int i = 0; i < 8; ++i)
            dst[i] = make_uint4(packed[4*i+0], packed[4*i+1], packed[4*i+2], packed[4*i+3]);
    } else {
        int g = (blockIdx.x - NB_PRE) * 256 + threadIdx.x;
        int q = g & (POST_N - 1);
        int b = g >> 12;
        const float* src = out_spikes + (size_t)b * POST_N + q;
        float tp = 0.0f, sacc = 0.0f;
        unsigned int packed[T_STEPS / 2];
#pragma unroll
        for (int t2 = 0; t2 < T_STEPS / 2; ++t2) {
            float o0 = src[(size_t)(2 * t2)     * (BATCH * POST_N)];
            float o1 = src[(size_t)(2 * t2 + 1) * (BATCH * POST_N)];
            tp = fmaf(0.5f, tp, o0);
            sacc = fmaf(o0, tp, sacc);
            float w0 = o0;
            tp = fmaf(0.5f, tp, o1);
            sacc = fmaf(o1, tp, sacc);
            __nv_bfloat162 h2 = __floats2bfloat162_rn(w0, o1);
            packed[t2] = *reinterpret_cast<unsigned int*>(&h2);
        }
        uint4* dst = reinterpret_cast<uint4*>(g_A + (size_t)q * KDIM + b * T_STEPS);
#pragma unroll
        for (int i = 0; i < 8; ++i)
            dst[i] = make_uint4(packed[4*i+0], packed[4*i+1], packed[4*i+2], packed[4*i+3]);
        g_spart[b * POST_N + q] = sacc;
    }
}

// ---------------------------------------------------------------------------
// PTX helpers
// ---------------------------------------------------------------------------
__device__ __forceinline__ void cp_async16(unsigned int saddr, const void* gptr) {
    asm volatile("cp.async.cg.shared.global [%0], [%1], 16;"
                 :: "r"(saddr), "l"(gptr) : "memory");
}

// .noinc: arrival count pre-accounted in mbarrier.init (256 producer threads).
// Arrives on mbar when all of this thread's prior cp.asyncs complete.
__device__ __forceinline__ void cp_async_mbar_arrive(unsigned int mbar) {
    asm volatile("cp.async.mbarrier.arrive.noinc.shared::cta.b64 [%0];"
                 :: "r"(mbar) : "memory");
}

__device__ __forceinline__ void mbar_init(unsigned int mbar, unsigned int cnt) {
    asm volatile("mbarrier.init.shared.b64 [%0], %1;" :: "r"(mbar), "r"(cnt) : "memory");
}

__device__ __forceinline__ void mbar_arrive(unsigned int mbar) {
    asm volatile("mbarrier.arrive.shared.b64 _, [%0];" :: "r"(mbar) : "memory");
}

#define MBAR_WAIT_PARITY(mbar_addr, parity) do {                                    \
    unsigned int _mbar = (unsigned int)(mbar_addr);                                 \
    unsigned int _par  = (unsigned int)(parity);                                    \
    unsigned int _done;                                                             \
    asm volatile(                                                                   \
        "{\n\t.reg .pred p;\n\t"                                                    \
        "mbarrier.try_wait.parity.acquire.cta.shared::cta.b64 p, [%1], %2;\n\t"     \
        "selp.b32 %0, 1, 0, p;\n\t}"                                                \
        : "=r"(_done) : "r"(_mbar), "r"(_par) : "memory");                          \
    if (!_done) {                                                                   \
        asm volatile(                                                               \
            "{\n\t.reg .pred P1;\n\t"                                               \
            "WAIT_LOOP_%=:\n\t"                                                     \
            "mbarrier.try_wait.parity.acquire.cta.shared::cta.b64 P1, [%0], %1, 0x989680;\n\t" \
            "@P1 bra.uni WAIT_DONE_%=;\n\t"                                         \
            "bra.uni WAIT_LOOP_%=;\n\t"                                             \
            "WAIT_DONE_%=:\n\t}"                                                    \
            :: "r"(_mbar), "r"(_par) : "memory");                                   \
    }                                                                               \
} while (0)

__device__ __forceinline__ void ldsm_x4(unsigned int& r0, unsigned int& r1,
                                        unsigned int& r2, unsigned int& r3,
                                        unsigned int addr) {
    asm volatile("ldmatrix.sync.aligned.m8n8.x4.shared.b16 {%0,%1,%2,%3}, [%4];"
                 : "=r"(r0), "=r"(r1), "=r"(r2), "=r"(r3) : "r"(addr));
}

__device__ __forceinline__ void mma16816(float* c,
                                         unsigned int a0, unsigned int a1,
                                         unsigned int a2, unsigned int a3,
                                         unsigned int b0, unsigned int b1) {
    asm volatile(
        "mma.sync.aligned.m16n8k16.row.col.f32.bf16.bf16.f32 "
        "{%0,%1,%2,%3}, {%4,%5,%6,%7}, {%8,%9}, {%0,%1,%2,%3};"
        : "+f"(c[0]), "+f"(c[1]), "+f"(c[2]), "+f"(c[3])
        : "r"(a0), "r"(a1), "r"(a2), "r"(a3), "r"(b0), "r"(b1));
}

// ---------------------------------------------------------------------------
// GEMM: D[128 x 128] CTA tile, 8 warps (2 M x 4 N), warp tile 64x32,
// 3-stage mbarrier pipeline (full: cp.async .noinc HW arrivals, count 256;
// empty: 256 consumer release arrivals), 2 CTAs/SM. No __syncthreads in the
// mainloop -> warps skew up to a chunk. Fused epilogue: acc - s[m]*W[m][n].
// mbar layout at MBAR_OFF: full[s] = +16s, empty[s] = +16s+8.
// ---------------------------------------------------------------------------
__global__ void __launch_bounds__(256, 2) stdp_gemm_kernel(
    const float* __restrict__ weight, float* __restrict__ out)
{
    extern __shared__ __align__(1024) char smem[];
    const unsigned int sbase = (unsigned int)__cvta_generic_to_shared(smem);
    const unsigned int mb = sbase + MBAR_OFF;
    const int tid = threadIdx.x;
    const int wid = tid >> 5;
    const int lid = tid & 31;
    const int n0 = blockIdx.x * TN;
    const int m0 = blockIdx.y * TM;

    const int warp_m = wid & 1;   // m offset 0/64
    const int warp_n = wid >> 1;  // n offset 0/32/64/96

    if (tid == 0) {
#pragma unroll
        for (int s = 0; s < NSTAGES; ++s) {
            mbar_init(mb + 16 * s,     256);   // full[s]  (cp.async .noinc arrivals)
            mbar_init(mb + 16 * s + 8, 256);   // empty[s] (consumer arrivals)
        }
    }
    __syncthreads();

    // ---- per-thread load addressing ----
    const int lm = tid >> 3;
    const int k8 = tid & 7;
    const unsigned int sw_base =
        (unsigned int)(lm * 128) + ((unsigned int)(k8 * 16) ^ ((lm & 7) << 4));
    const __nv_bfloat16* pa = g_A + (size_t)(m0 + lm) * KDIM + k8 * 8;
    const __nv_bfloat16* pb = g_B + (size_t)(n0 + lm) * KDIM + k8 * 8;

    // produce one chunk into stage ps: 8 cp.asyncs + .noinc arrive on full[ps]
    auto produce = [&](const __nv_bfloat16* a, const __nv_bfloat16* b, int ps) {
        const unsigned int sa = sbase + ps * STAGE_BYTES + sw_base;
#pragma unroll
        for (int i = 0; i < 4; ++i)
            cp_async16(sa + i * 4096, a + (size_t)i * 32 * KDIM);
        const unsigned int sb = sa + A_STAGE_BYTES;
#pragma unroll
        for (int i = 0; i < 4; ++i)
            cp_async16(sb + i * 4096, b + (size_t)i * 32 * KDIM);
        cp_async_mbar_arrive(mb + 16 * ps);
    };

    // ---- ldmatrix lane addressing ----
    const int q  = lid >> 3;
    const int r  = lid & 7;
    const int lrow = (q & 1) * 8 + r;
    const int lkb  = (q >> 1) * 16;
    unsigned int kxor[4];
#pragma unroll
    for (int ks = 0; ks < 4; ++ks)
        kxor[ks] = (unsigned int)((ks * 32 + lkb) ^ (r << 4));
    const unsigned int a_rowbase = (unsigned int)((warp_m * 64 + lrow) * 128);
    const unsigned int b_rowbase = (unsigned int)((warp_n * 32 + lrow) * 128);

    float acc[4][4][4];
#pragma unroll
    for (int mt = 0; mt < 4; ++mt)
#pragma unroll
        for (int nt = 0; nt < 4; ++nt)
#pragma unroll
            for (int j = 0; j < 4; ++j) acc[mt][nt][j] = 0.0f;

    // pipeline cursors: producer starts phase 1 (fresh-barrier wait passes)
    int ps = 0, pp = 1, cs = 0, cphase = 0;

    // ---- prologue: produce chunks 0,1 ----
    MBAR_WAIT_PARITY(mb + 16 * ps + 8, pp);
    produce(pa, pb, ps);
    ++ps;                                  // 1, no wrap
    MBAR_WAIT_PARITY(mb + 16 * ps + 8, pp);
    produce(pa + KC, pb + KC, ps);
    ++ps;                                  // 2
    pa += 2 * KC; pb += 2 * KC;            // point at chunk 2

    // ---- mainloop ----
    for (int c = 0; c < NCHUNK; ++c) {
        if (c + 2 < NCHUNK) {
            MBAR_WAIT_PARITY(mb + 16 * ps + 8, pp);   // empty[ps]
            produce(pa, pb, ps);
            pa += KC; pb += KC;
            if (++ps == NSTAGES) { ps = 0; pp ^= 1; }
        }

        MBAR_WAIT_PARITY(mb + 16 * cs, cphase);       // full[cs] (acquire)
        const unsigned int sa = sbase + cs * STAGE_BYTES;
        const unsigned int sb = sa + A_STAGE_BYTES;

#pragma unroll
        for (int ks = 0; ks < 4; ++ks) {
            unsigned int af[4][4], bf[2][4];
#pragma unroll
            for (int mt = 0; mt < 4; ++mt)
                ldsm_x4(af[mt][0], af[mt][1], af[mt][2], af[mt][3],
                        sa + a_rowbase + mt * 2048 + kxor[ks]);
#pragma unroll
            for (int nt2 = 0; nt2 < 2; ++nt2)
                ldsm_x4(bf[nt2][0], bf[nt2][1], bf[nt2][2], bf[nt2][3],
                        sb + b_rowbase + nt2 * 2048 + kxor[ks]);
#pragma unroll
            for (int mt = 0; mt < 4; ++mt)
#pragma unroll
                for (int nt2 = 0; nt2 < 2; ++nt2) {
                    mma16816(acc[mt][2 * nt2],
                             af[mt][0], af[mt][1], af[mt][2], af[mt][3],
                             bf[nt2][0], bf[nt2][2]);
                    mma16816(acc[mt][2 * nt2 + 1],
                             af[mt][0], af[mt][1], af[mt][2], af[mt][3],
                             bf[nt2][1], bf[nt2][3]);
                }
        }

        mbar_arrive(mb + 16 * cs + 8);                // empty[cs] (release)
        if (++cs == NSTAGES) { cs = 0; cphase ^= 1; }
    }

    // ---- fused epilogue: out = acc - s[m] * W[m][n]; s from g_spart ----
    const int tid4 = lid >> 2;
    const int tp   = lid & 3;
#pragma unroll
    for (int mt = 0; mt < 4; ++mt) {
#pragma unroll
        for (int half = 0; half < 2; ++half) {
            const int gm = m0 + warp_m * 64 + mt * 16 + half * 8 + tid4;
            float sv = 0.0f;
#pragma unroll
            for (int b = 0; b < BATCH; ++b) sv += __ldg(&g_spart[b * POST_N + gm]);
            const float* wrow = weight + (size_t)gm * PRE_N + n0 + warp_n * 32;
            float* orow       = out    + (size_t)gm * PRE_N + n0 + warp_n * 32;
#pragma unroll
            for (int nt = 0; nt < 4; ++nt) {
                const int col = nt * 8 + 2 * tp;
                float2 w2 = *reinterpret_cast<const float2*>(wrow + col);
                float2 o2;
                o2.x = acc[mt][nt][2 * half + 0] - sv * w2.x;
                o2.y = acc[mt][nt][2 * half + 1] - sv * w2.y;
                *reinterpret_cast<float2*>(orow + col) = o2;
            }
        }
    }
}

// ---------------------------------------------------------------------------
extern "C" void kernel_launch(void* const* d_in, const int* in_sizes, int n_in,
                              void* d_out, int out_size) {
    (void)in_sizes; (void)n_in; (void)out_size;
    const float* in_spikes  = (const float*)d_in[0];
    const float* out_spikes = (const float*)d_in[1];
    const float* weight     = (const float*)d_in[2];
    float* out = (float*)d_out;

    cudaFuncSetAttribute(stdp_gemm_kernel,
                         cudaFuncAttributeMaxDynamicSharedMemorySize, SMEM_TOTAL);

    prep_kernel<<<NB_PRE + NB_POST, 256>>>(in_spikes, out_spikes);

    dim3 grid(PRE_N / TN, POST_N / TM);
    stdp_gemm_kernel<<<grid, 256, SMEM_TOTAL>>>(weight, out);
}

// round 13
// speedup vs baseline: 1.0269x; 1.0269x over previous
#include <cuda_runtime.h>
#include <cuda_bf16.h>
#include <cstdint>
#include <cstddef>

// ---------------------------------------------------------------------------
// STDP delta_w:
//   delta_w = sum_t O_t^T P_t  -  s[:,None] * W
// GEMM: K = T*B = 1024, M = POST = 4096, N = PRE = 4096, HMMA mma.sync bf16.
// R13: R7 skeleton (best: 105.5us GEMM) + two tail optimizations:
//  (a) per-CTA s[] reduced ONCE at prologue into smem (was 128 __ldg/thread
//      serialized after the mainloop),
//  (b) W tile L2-prefetch spread over mainloop chunks (epilogue W-loads were
//      cold DRAM while the DRAM pipe idled at 14%).
// Mainloop untouched: R6/R7/R10/R12 all plateau at ~53% tensor; pipeline
// variants are noise. (R12 mbarrier == R7 syncthreads: 106.6 vs 105.5.)
// ---------------------------------------------------------------------------

namespace {
constexpr int T_STEPS = 64;
constexpr int BATCH   = 16;
constexpr int PRE_N   = 4096;
constexpr int POST_N  = 4096;
constexpr int KDIM    = T_STEPS * BATCH;  // 1024

constexpr int TM = 128;
constexpr int TN = 128;
constexpr int KC = 64;                       // K elems per chunk (128 B rows)
constexpr int NCHUNK  = KDIM / KC;           // 16
constexpr int NSTAGES = 3;
constexpr int A_STAGE_BYTES = TM * 128;      // 16384
constexpr int B_STAGE_BYTES = TN * 128;      // 16384
constexpr int STAGE_BYTES   = A_STAGE_BYTES + B_STAGE_BYTES;   // 32768
constexpr int S_OFF         = NSTAGES * STAGE_BYTES;           // 98304
constexpr int SMEM_TOTAL    = S_OFF + TM * 4;                  // +512 for s[]

constexpr int NB_PRE  = (BATCH * PRE_N)  / 256;  // 256
constexpr int NB_POST = (BATCH * POST_N) / 256;  // 256
}

// Scratch (device globals: allocation-free rule)
__device__ __nv_bfloat16 g_A[POST_N * KDIM];   // out_spikes^T bf16 [post][k]
__device__ __nv_bfloat16 g_B[PRE_N * KDIM];    // trace_pre^T bf16 [pre][k]
__device__ float g_spart[BATCH * POST_N];

// ---------------------------------------------------------------------------
// Combined preprocess (one launch):
//  blocks [0, NB_PRE)             : trace_pre scan -> g_B (K-major bf16)
//  blocks [NB_PRE, NB_PRE+NB_POST): out_spikes^T   -> g_A + s partials
// ---------------------------------------------------------------------------
__global__ void __launch_bounds__(256) prep_kernel(
    const float* __restrict__ in_spikes, const float* __restrict__ out_spikes)
{
    if (blockIdx.x < NB_PRE) {
        int g = blockIdx.x * 256 + threadIdx.x;
        int p = g & (PRE_N - 1);
        int b = g >> 12;
        const float* src = in_spikes + (size_t)b * PRE_N + p;
        float tp = 0.0f;
        unsigned int packed[T_STEPS / 2];
#pragma unroll
        for (int t2 = 0; t2 < T_STEPS / 2; ++t2) {
            float i0 = src[(size_t)(2 * t2)     * (BATCH * PRE_N)];
            float i1 = src[(size_t)(2 * t2 + 1) * (BATCH * PRE_N)];
            tp = fminf(fmaxf(fmaf(0.5f, tp, i0), 0.0f), 1.0f);
            float v0 = tp;
            tp = fminf(fmaxf(fmaf(0.5f, tp, i1), 0.0f), 1.0f);
            float v1 = tp;
            __nv_bfloat162 h2 = __floats2bfloat162_rn(v0, v1);
            packed[t2] = *reinterpret_cast<unsigned int*>(&h2);
        }
        uint4* dst = reinterpret_cast<uint4*>(g_B + (size_t)p * KDIM + b * T_STEPS);
#pragma unroll
        for (int i = 0; i < 8; ++i)
            dst[i] = make_uint4(packed[4*i+0], packed[4*i+1], packed[4*i+2], packed[4*i+3]);
    } else {
        int g = (blockIdx.x - NB_PRE) * 256 + threadIdx.x;
        int q = g & (POST_N - 1);
        int b = g >> 12;
        const float* src = out_spikes + (size_t)b * POST_N + q;
        float tp = 0.0f, sacc = 0.0f;
        unsigned int packed[T_STEPS / 2];
#pragma unroll
        for (int t2 = 0; t2 < T_STEPS / 2; ++t2) {
            float o0 = src[(size_t)(2 * t2)     * (BATCH * POST_N)];
            float o1 = src[(size_t)(2 * t2 + 1) * (BATCH * POST_N)];
            tp = fmaf(0.5f, tp, o0);
            sacc = fmaf(o0, tp, sacc);
            float w0 = o0;
            tp = fmaf(0.5f, tp, o1);
            sacc = fmaf(o1, tp, sacc);
            __nv_bfloat162 h2 = __floats2bfloat162_rn(w0, o1);
            packed[t2] = *reinterpret_cast<unsigned int*>(&h2);
        }
        uint4* dst = reinterpret_cast<uint4*>(g_A + (size_t)q * KDIM + b * T_STEPS);
#pragma unroll
        for (int i = 0; i < 8; ++i)
            dst[i] = make_uint4(packed[4*i+0], packed[4*i+1], packed[4*i+2], packed[4*i+3]);
        g_spart[b * POST_N + q] = sacc;
    }
}

// ---------------------------------------------------------------------------
// PTX helpers
// ---------------------------------------------------------------------------
__device__ __forceinline__ void cp_async16(unsigned int saddr, const void* gptr) {
    asm volatile("cp.async.cg.shared.global [%0], [%1], 16;"
                 :: "r"(saddr), "l"(gptr) : "memory");
}

__device__ __forceinline__ void l2_prefetch(const void* gptr) {
    asm volatile("prefetch.global.L2 [%0];" :: "l"(gptr));
}

__device__ __forceinline__ void ldsm_x4(unsigned int& r0, unsigned int& r1,
                                        unsigned int& r2, unsigned int& r3,
                                        unsigned int addr) {
    asm volatile("ldmatrix.sync.aligned.m8n8.x4.shared.b16 {%0,%1,%2,%3}, [%4];"
                 : "=r"(r0), "=r"(r1), "=r"(r2), "=r"(r3) : "r"(addr));
}

__device__ __forceinline__ void mma16816(float* c,
                                         unsigned int a0, unsigned int a1,
                                         unsigned int a2, unsigned int a3,
                                         unsigned int b0, unsigned int b1) {
    asm volatile(
        "mma.sync.aligned.m16n8k16.row.col.f32.bf16.bf16.f32 "
        "{%0,%1,%2,%3}, {%4,%5,%6,%7}, {%8,%9}, {%0,%1,%2,%3};"
        : "+f"(c[0]), "+f"(c[1]), "+f"(c[2]), "+f"(c[3])
        : "r"(a0), "r"(a1), "r"(a2), "r"(a3), "r"(b0), "r"(b1));
}

// ---------------------------------------------------------------------------
// GEMM: D[128 x 128] CTA tile, 8 warps (2 M x 4 N), warp tile 64x32,
// 3-stage cp.async pipeline (wait_group 1), 2 CTAs/SM (16 warps/SM).
// cp.async issues interleaved into the ks loop (2 per ks).
// Prologue: per-CTA s[128] reduced into smem. Mainloop: W tile L2-prefetch.
// Fused epilogue: out = acc - s[m] * W[m][n], s from smem.
// ---------------------------------------------------------------------------
__global__ void __launch_bounds__(256, 2) stdp_gemm_kernel(
    const float* __restrict__ weight, float* __restrict__ out)
{
    extern __shared__ __align__(1024) char smem[];
    const unsigned int sbase = (unsigned int)__cvta_generic_to_shared(smem);
    float* s_sm = reinterpret_cast<float*>(smem + S_OFF);
    const int tid = threadIdx.x;
    const int wid = tid >> 5;
    const int lid = tid & 31;
    const int n0 = blockIdx.x * TN;
    const int m0 = blockIdx.y * TM;

    const int warp_m = wid & 1;   // m offset 0/64
    const int warp_n = wid >> 1;  // n offset 0/32/64/96

    // ---- per-thread load addressing ----
    const int lm = tid >> 3;
    const int k8 = tid & 7;
    const unsigned int sw_base =
        (unsigned int)(lm * 128) + ((unsigned int)(k8 * 16) ^ ((lm & 7) << 4));
    const __nv_bfloat16* pa = g_A + (size_t)(m0 + lm) * KDIM + k8 * 8;
    const __nv_bfloat16* pb = g_B + (size_t)(n0 + lm) * KDIM + k8 * 8;

    auto load_chunk_full = [&](const __nv_bfloat16* a, const __nv_bfloat16* b, int st) {
        const unsigned int sa = sbase + st * STAGE_BYTES + sw_base;
#pragma unroll
        for (int i = 0; i < 4; ++i)
            cp_async16(sa + i * 4096, a + (size_t)i * 32 * KDIM);
        const unsigned int sb = sa + A_STAGE_BYTES;
#pragma unroll
        for (int i = 0; i < 4; ++i)
            cp_async16(sb + i * 4096, b + (size_t)i * 32 * KDIM);
    };

    // ---- ldmatrix lane addressing ----
    const int q  = lid >> 3;
    const int r  = lid & 7;
    const int lrow = (q & 1) * 8 + r;
    const int lkb  = (q >> 1) * 16;
    unsigned int kxor[4];
#pragma unroll
    for (int ks = 0; ks < 4; ++ks)
        kxor[ks] = (unsigned int)((ks * 32 + lkb) ^ (r << 4));
    const unsigned int a_rowbase = (unsigned int)((warp_m * 64 + lrow) * 128);
    const unsigned int b_rowbase = (unsigned int)((warp_n * 32 + lrow) * 128);

    float acc[4][4][4];
#pragma unroll
    for (int mt = 0; mt < 4; ++mt)
#pragma unroll
        for (int nt = 0; nt < 4; ++nt)
#pragma unroll
            for (int j = 0; j < 4; ++j) acc[mt][nt][j] = 0.0f;

    // ---- prologue: chunks 0,1 -> stages 0,1 ----
    load_chunk_full(pa, pb, 0);
    asm volatile("cp.async.commit_group;" ::: "memory");
    load_chunk_full(pa + KC, pb + KC, 1);
    asm volatile("cp.async.commit_group;" ::: "memory");
    pa += 2 * KC; pb += 2 * KC;   // point at chunk 2 (next prefetch)

    // ---- prologue: reduce this CTA's s[128] into smem (overlaps load wait) ----
    if (tid < TM) {
        float sv = 0.0f;
#pragma unroll
        for (int b = 0; b < BATCH; ++b) sv += __ldg(&g_spart[b * POST_N + m0 + tid]);
        s_sm[tid] = sv;
    }

    // W prefetch base for this warp's epilogue region (64 rows x 1 line)
    const float* wpf = weight + (size_t)(m0 + warp_m * 64) * PRE_N + n0 + warp_n * 32;

    int st = 0;
    // ---- mainloop ----
    for (int c = 0; c < NCHUNK; ++c) {
        asm volatile("cp.async.wait_group 1;" ::: "memory");
        __syncthreads();   // chunk c visible; all warps done with stage st2
                           // (also publishes s_sm before the epilogue)

        const unsigned int sa = sbase + st * STAGE_BYTES;
        const unsigned int sb = sa + A_STAGE_BYTES;
        int st2 = st + 2; if (st2 >= NSTAGES) st2 -= NSTAGES;   // stage for c+2
        const unsigned int spa = sbase + st2 * STAGE_BYTES + sw_base;
        const unsigned int spb = spa + A_STAGE_BYTES;
        const bool do_load = (c + 2 < NCHUNK);

        // L2-prefetch 4 rows of this warp's W epilogue tile per chunk
        if (lid < 4)
            l2_prefetch(wpf + (size_t)(c * 4 + lid) * PRE_N);

#pragma unroll
        for (int ks = 0; ks < 4; ++ks) {
            unsigned int af[4][4], bf[2][4];
#pragma unroll
            for (int mt = 0; mt < 4; ++mt)
                ldsm_x4(af[mt][0], af[mt][1], af[mt][2], af[mt][3],
                        sa + a_rowbase + mt * 2048 + kxor[ks]);
#pragma unroll
            for (int nt2 = 0; nt2 < 2; ++nt2)
                ldsm_x4(bf[nt2][0], bf[nt2][1], bf[nt2][2], bf[nt2][3],
                        sb + b_rowbase + nt2 * 2048 + kxor[ks]);

            // spread chunk-(c+2) loads: 2 cp.asyncs per ks
            if (do_load) {
                if (ks == 0) {
                    cp_async16(spa,        pa);
                    cp_async16(spa + 4096, pa + (size_t)32 * KDIM);
                } else if (ks == 1) {
                    cp_async16(spa + 8192,  pa + (size_t)64 * KDIM);
                    cp_async16(spa + 12288, pa + (size_t)96 * KDIM);
                } else if (ks == 2) {
                    cp_async16(spb,        pb);
                    cp_async16(spb + 4096, pb + (size_t)32 * KDIM);
                } else {
                    cp_async16(spb + 8192,  pb + (size_t)64 * KDIM);
                    cp_async16(spb + 12288, pb + (size_t)96 * KDIM);
                }
            }

#pragma unroll
            for (int mt = 0; mt < 4; ++mt)
#pragma unroll
                for (int nt2 = 0; nt2 < 2; ++nt2) {
                    mma16816(acc[mt][2 * nt2],
                             af[mt][0], af[mt][1], af[mt][2], af[mt][3],
                             bf[nt2][0], bf[nt2][2]);
                    mma16816(acc[mt][2 * nt2 + 1],
                             af[mt][0], af[mt][1], af[mt][2], af[mt][3],
                             bf[nt2][1], bf[nt2][3]);
                }
        }
        asm volatile("cp.async.commit_group;" ::: "memory");
        pa += KC; pb += KC;
        if (++st == NSTAGES) st = 0;
    }

    // ---- fused epilogue: out = acc - s[m] * W[m][n]; s from smem ----
    const int tid4 = lid >> 2;
    const int tp   = lid & 3;
#pragma unroll
    for (int mt = 0; mt < 4; ++mt) {
#pragma unroll
        for (int half = 0; half < 2; ++half) {
            const int lrow_ep = warp_m * 64 + mt * 16 + half * 8 + tid4;
            const int gm = m0 + lrow_ep;
            const float sv = s_sm[lrow_ep];
            const float* wrow = weight + (size_t)gm * PRE_N + n0 + warp_n * 32;
            float* orow       = out    + (size_t)gm * PRE_N + n0 + warp_n * 32;
#pragma unroll
            for (int nt = 0; nt < 4; ++nt) {
                const int col = nt * 8 + 2 * tp;
                float2 w2 = *reinterpret_cast<const float2*>(wrow + col);
                float2 o2;
                o2.x = acc[mt][nt][2 * half + 0] - sv * w2.x;
                o2.y = acc[mt][nt][2 * half + 1] - sv * w2.y;
                *reinterpret_cast<float2*>(orow + col) = o2;
            }
        }
    }
}

// ---------------------------------------------------------------------------
extern "C" void kernel_launch(void* const* d_in, const int* in_sizes, int n_in,
                              void* d_out, int out_size) {
    (void)in_sizes; (void)n_in; (void)out_size;
    const float* in_spikes  = (const float*)d_in[0];
    const float* out_spikes = (const float*)d_in[1];
    const float* weight     = (const float*)d_in[2];
    float* out = (float*)d_out;

    cudaFuncSetAttribute(stdp_gemm_kernel,
                         cudaFuncAttributeMaxDynamicSharedMemorySize, SMEM_TOTAL);

    prep_kernel<<<NB_PRE + NB_POST, 256>>>(in_spikes, out_spikes);

    dim3 grid(PRE_N / TN, POST_N / TM);
    stdp_gemm_kernel<<<grid, 256, SMEM_TOTAL>>>(weight, out);
}